// round 2
// baseline (speedup 1.0000x reference)
#include <cuda_runtime.h>

// Pull_37091337568590: 2D linear-interp warp, wrap boundary.
// x: [8,16,512,512] f32, phi: [8,2,512,512] f32, out: [8,16,512,512] f32.
//
// R2 strategy: per-(channel,tile) shared-memory staging. The naive gather is
// L1tex-wavefront-bound because lanes diverge in y (each distinct y0 is a
// distinct 128B line). LDS taps from a staged tile cost ~1-2 cyc/warp
// independent of y-divergence. Halo = 8 voxels; displacements beyond the halo
// (P ~ 0.4%/side, dy~N(0,3)) fall back to a correct global wrap-gather.

#define PB 8
#define PC 16
#define PH 512
#define PW 512
#define PHW (PH * PW)

#define TW 64
#define TH 64
#define HR 8
#define SW (TW + 2 * HR)      // 80
#define SH (TH + 2 * HR)      // 80
#define SSTR 81               // pad: 81 mod 32 = 17 -> decorrelates banks

__global__ __launch_bounds__(256)
void pull_tile_kernel(const float* __restrict__ x,
                      const float* __restrict__ phi,
                      float* __restrict__ out)
{
    __shared__ float tile[SH * SSTR];

    const int tx0 = blockIdx.x * TW;
    const int ty0 = blockIdx.y * TH;
    const int b   = blockIdx.z;
    const int tid = threadIdx.x;

    const int px = tid & (TW - 1);   // 0..63
    const int py = tid >> 6;         // 0..3

    const float* __restrict__ phiy = phi + (size_t)b * 2 * PHW;
    const float* __restrict__ phix = phiy + PHW;
    const float* __restrict__ xb   = x   + (size_t)b * PC * PHW;
    float* __restrict__ ob         = out + (size_t)b * PC * PHW;

    for (int c = 0; c < PC; c++) {
        const float* __restrict__ xc = xb + c * PHW;

        __syncthreads();   // protect tile from previous iteration's readers
        // ---- fill smem tile (wrapped rows/cols), coalesced ----
        for (int i = tid; i < SH * SW; i += 256) {
            int r   = i / SW;
            int col = i - r * SW;
            int gr = (ty0 - HR + r)   & (PH - 1);
            int gc = (tx0 - HR + col) & (PW - 1);
            tile[r * SSTR + col] = __ldg(xc + gr * PW + gc);
        }
        __syncthreads();

        float* __restrict__ oc = ob + c * PHW;

        #pragma unroll
        for (int i = 0; i < TH / 4; i++) {
            int h = ty0 + py + i * 4;
            int w = tx0 + px;
            int p = h * PW + w;

            float dy = __ldg(phiy + p);
            float dx = __ldg(phix + p);
            float cy = dy + (float)h;
            float cx = dx + (float)w;

            float y0f = floorf(cy);
            float x0f = floorf(cx);
            float wy = cy - y0f;
            float wx = cx - x0f;

            int y0 = (int)y0f;
            int x0 = (int)x0f;

            int sy = y0 - (ty0 - HR);   // unwrapped tile-local coords
            int sx = x0 - (tx0 - HR);

            float v00, v01, v10, v11;
            if ((unsigned)sy < (SH - 1) && (unsigned)sx < (SW - 1)) {
                const float* t = tile + sy * SSTR + sx;
                v00 = t[0];
                v01 = t[1];
                v10 = t[SSTR];
                v11 = t[SSTR + 1];
            } else {
                // rare fallback: displacement beyond halo -> global wrap gather
                int yy0 = y0 & (PH - 1);
                int xx0 = x0 & (PW - 1);
                int yy1 = (yy0 + 1) & (PH - 1);
                int xx1 = (xx0 + 1) & (PW - 1);
                v00 = __ldg(xc + yy0 * PW + xx0);
                v01 = __ldg(xc + yy0 * PW + xx1);
                v10 = __ldg(xc + yy1 * PW + xx0);
                v11 = __ldg(xc + yy1 * PW + xx1);
            }

            float w00 = (1.0f - wy) * (1.0f - wx);
            float w01 = (1.0f - wy) * wx;
            float w10 = wy * (1.0f - wx);
            float w11 = wy * wx;

            oc[p] = v00 * w00 + v01 * w01 + v10 * w10 + v11 * w11;
        }
    }
}

extern "C" void kernel_launch(void* const* d_in, const int* in_sizes, int n_in,
                              void* d_out, int out_size)
{
    const float* x   = (const float*)d_in[0];
    const float* phi = (const float*)d_in[1];
    float* out = (float*)d_out;

    dim3 grid(PW / TW, PH / TH, PB);   // 8 x 8 x 8 = 512 blocks
    pull_tile_kernel<<<grid, 256>>>(x, phi, out);
}

// round 3
// speedup vs baseline: 1.1278x; 1.1278x over previous
#include <cuda_runtime.h>

// Pull_37091337568590, R3: smem tile + hoisted per-pixel coords.
// x: [8,16,512,512] f32, phi: [8,2,512,512] f32, out: [8,16,512,512] f32.
//
// Phase 1 (once per block): compute sample coords/weights for all 4096 pixels
// of a 64x64 tile, store packed in smem (u32 tile-offset or fallback coords,
// wy, wx). Phase 2 (per channel): stage 80x80 halo tile in smem, blend with
// 4 LDS taps. Fallback (displacement beyond 8-voxel halo, ~1% of pixels):
// packed global wrapped coords, gathered via LDG.

#define PB 8
#define PC 16
#define PH 512
#define PW 512
#define PHW (PH * PW)

#define TW 64
#define TH 64
#define HR 8
#define SW (TW + 2 * HR)      // 80
#define SH (TH + 2 * HR)      // 80
#define SSTR 81               // row stride (pad)
#define NPX (TW * TH)         // 4096
#define NT 512                // threads per block

__global__ __launch_bounds__(NT)
void pull_tile2_kernel(const float* __restrict__ x,
                       const float* __restrict__ phi,
                       float* __restrict__ out)
{
    __shared__ float tile[SH * SSTR];        // 25.9 KB
    __shared__ unsigned csel[NPX];           // 16 KB  packed offset / fallback
    __shared__ float cwy[NPX];               // 16 KB
    __shared__ float cwx[NPX];               // 16 KB

    const int tx0 = blockIdx.x * TW;
    const int ty0 = blockIdx.y * TH;
    const int b   = blockIdx.z;
    const int tid = threadIdx.x;

    const int px = tid & (TW - 1);           // 0..63
    const int py = tid >> 6;                 // 0..7

    const float* __restrict__ phiy = phi + (size_t)b * 2 * PHW;
    const float* __restrict__ phix = phiy + PHW;
    const float* __restrict__ xb   = x   + (size_t)b * PC * PHW;
    float* __restrict__ ob         = out + (size_t)b * PC * PHW;

    // ---- Phase 1: coords for 4096 pixels, once ----
    #pragma unroll
    for (int i = 0; i < TH / 8; i++) {       // 8 pixels per thread
        int ly = py + i * 8;                 // tile-local row
        int h = ty0 + ly;
        int w = tx0 + px;
        int p = h * PW + w;

        float cy = __ldg(phiy + p) + (float)h;
        float cx = __ldg(phix + p) + (float)w;
        float y0f = floorf(cy);
        float x0f = floorf(cx);
        int li = ly * TW + px;
        cwy[li] = cy - y0f;
        cwx[li] = cx - x0f;

        int y0 = (int)y0f;
        int x0 = (int)x0f;
        int sy = y0 - (ty0 - HR);
        int sx = x0 - (tx0 - HR);

        unsigned sel;
        if ((unsigned)sy < (SH - 1) && (unsigned)sx < (SW - 1)) {
            sel = (unsigned)(sy * SSTR + sx);            // in-tile offset
        } else {
            // fallback: wrapped global coords + flag bit
            sel = 0x80000000u | ((unsigned)(y0 & (PH - 1)) << 9)
                              |  (unsigned)(x0 & (PW - 1));
        }
        csel[li] = sel;
    }
    __syncthreads();

    // ---- Phase 2: per channel stage + blend ----
    for (int c = 0; c < PC; c++) {
        const float* __restrict__ xc = xb + c * PHW;
        float* __restrict__ oc       = ob + c * PHW;

        // fill 80x80 halo tile, coalesced
        for (int i = tid; i < SH * SW; i += NT) {
            int r   = i / SW;
            int col = i - r * SW;
            int gr = (ty0 - HR + r)   & (PH - 1);
            int gc = (tx0 - HR + col) & (PW - 1);
            tile[r * SSTR + col] = __ldg(xc + gr * PW + gc);
        }
        __syncthreads();

        #pragma unroll
        for (int i = 0; i < TH / 8; i++) {
            int ly = py + i * 8;
            int li = ly * TW + px;
            unsigned sel = csel[li];
            float wy = cwy[li];
            float wx = cwx[li];

            float v00, v01, v10, v11;
            if (!(sel & 0x80000000u)) {
                const float* t = tile + sel;
                v00 = t[0];
                v01 = t[1];
                v10 = t[SSTR];
                v11 = t[SSTR + 1];
            } else {
                int y0 = (int)((sel >> 9) & (PH - 1));
                int x0 = (int)(sel & (PW - 1));
                int y1 = (y0 + 1) & (PH - 1);
                int x1 = (x0 + 1) & (PW - 1);
                v00 = __ldg(xc + y0 * PW + x0);
                v01 = __ldg(xc + y0 * PW + x1);
                v10 = __ldg(xc + y1 * PW + x0);
                v11 = __ldg(xc + y1 * PW + x1);
            }

            float top = v00 + wx * (v01 - v00);
            float bot = v10 + wx * (v11 - v10);
            float v   = top + wy * (bot - top);

            oc[(ty0 + ly) * PW + (tx0 + px)] = v;
        }
        __syncthreads();   // before next channel overwrites tile
    }
}

extern "C" void kernel_launch(void* const* d_in, const int* in_sizes, int n_in,
                              void* d_out, int out_size)
{
    const float* x   = (const float*)d_in[0];
    const float* phi = (const float*)d_in[1];
    float* out = (float*)d_out;

    dim3 grid(PW / TW, PH / TH, PB);   // 8 x 8 x 8 = 512 blocks
    pull_tile2_kernel<<<grid, NT>>>(x, phi, out);
}

// round 4
// speedup vs baseline: 2.0925x; 1.8553x over previous
#include <cuda_runtime.h>
#include <cuda_pipeline.h>

// Pull_37091337568590, R4: smem tile + cp.async double-buffered channel fill
// + register-resident per-pixel coords.
// x: [8,16,512,512] f32, phi: [8,2,512,512] f32, out: [8,16,512,512] f32.

#define PB 8
#define PC 16
#define PH 512
#define PW 512
#define PHW (PH * PW)

#define TW 64
#define TH 64
#define HR 8
#define SW (TW + 2 * HR)      // 80 floats per tile row
#define SH (TH + 2 * HR)      // 80 rows
#define SSTR 84               // row stride in floats: mult of 4 (16B cp.async), %32=20
#define TILE_FLOATS (SH * SSTR)
#define NT 512
#define NPPT 8                // pixels per thread (TH*TW / NT)

__global__ __launch_bounds__(NT)
void pull_tile3_kernel(const float* __restrict__ x,
                       const float* __restrict__ phi,
                       float* __restrict__ out)
{
    extern __shared__ float smem[];
    float* buf[2] = { smem, smem + TILE_FLOATS };

    const int tx0 = blockIdx.x * TW;
    const int ty0 = blockIdx.y * TH;
    const int b   = blockIdx.z;
    const int tid = threadIdx.x;

    const int px = tid & (TW - 1);   // 0..63
    const int py = tid >> 6;         // 0..7

    const float* __restrict__ phiy = phi + (size_t)b * 2 * PHW;
    const float* __restrict__ phix = phiy + PHW;
    const float* __restrict__ xb   = x   + (size_t)b * PC * PHW;
    float* __restrict__ ob         = out + (size_t)b * PC * PHW;

    // ---- fill-lane mapping (no divisions) ----
    const int fr   = tid >> 5;        // 0..15  (row within 16-row pass)
    const int fc4  = tid & 31;        // float4 index, active when < SW/4=20
    const bool factive = (fc4 < SW / 4);
    // gmem column for this lane's float4 (never crosses wrap inside the 4)
    const int gcol = (tx0 - HR + fc4 * 4) & (PW - 1);

    // ---- per-pixel coords in registers ----
    unsigned sel[NPPT];
    float    fwy[NPPT], fwx[NPPT];
    #pragma unroll
    for (int i = 0; i < NPPT; i++) {
        int ly = py + i * 8;
        int h  = ty0 + ly;
        int w  = tx0 + px;
        int p  = h * PW + w;

        float cy = __ldg(phiy + p) + (float)h;
        float cx = __ldg(phix + p) + (float)w;
        float y0f = floorf(cy);
        float x0f = floorf(cx);
        fwy[i] = cy - y0f;
        fwx[i] = cx - x0f;

        int y0 = (int)y0f;
        int x0 = (int)x0f;
        int sy = y0 - (ty0 - HR);
        int sx = x0 - (tx0 - HR);

        if ((unsigned)sy < (SH - 1) && (unsigned)sx < (SW - 1)) {
            sel[i] = (unsigned)((sy * SSTR + sx) * 4);      // byte offset in tile
        } else {
            sel[i] = 0x80000000u | ((unsigned)(y0 & (PH - 1)) << 9)
                                 |  (unsigned)(x0 & (PW - 1));
        }
    }

    // ---- prefetch channel 0 ----
    {
        const float* xc = xb;
        #pragma unroll
        for (int pass = 0; pass < SH / 16; pass++) {
            int r  = fr + pass * 16;
            int gr = (ty0 - HR + r) & (PH - 1);
            if (factive)
                __pipeline_memcpy_async(buf[0] + r * SSTR + fc4 * 4,
                                        xc + gr * PW + gcol, 16);
        }
        __pipeline_commit();
    }

    // ---- per-channel: wait, prefetch next, blend ----
    for (int c = 0; c < PC; c++) {
        const float* __restrict__ xc = xb + c * PHW;
        float* __restrict__ oc       = ob + c * PHW;
        const float* __restrict__ cur = buf[c & 1];

        __pipeline_wait_prior(0);
        __syncthreads();          // all fills visible; prev blend readers done

        if (c + 1 < PC) {
            const float* xn = xc + PHW;
            float* nb = buf[(c + 1) & 1];
            #pragma unroll
            for (int pass = 0; pass < SH / 16; pass++) {
                int r  = fr + pass * 16;
                int gr = (ty0 - HR + r) & (PH - 1);
                if (factive)
                    __pipeline_memcpy_async(nb + r * SSTR + fc4 * 4,
                                            xn + gr * PW + gcol, 16);
            }
            __pipeline_commit();
        }

        #pragma unroll
        for (int i = 0; i < NPPT; i++) {
            unsigned s = sel[i];
            float wy = fwy[i];
            float wx = fwx[i];

            float v00, v01, v10, v11;
            if (!(s & 0x80000000u)) {
                const float* t = (const float*)((const char*)cur + s);
                v00 = t[0];
                v01 = t[1];
                v10 = t[SSTR];
                v11 = t[SSTR + 1];
            } else {
                int y0 = (int)((s >> 9) & (PH - 1));
                int x0 = (int)(s & (PW - 1));
                int y1 = (y0 + 1) & (PH - 1);
                int x1 = (x0 + 1) & (PW - 1);
                v00 = __ldg(xc + y0 * PW + x0);
                v01 = __ldg(xc + y0 * PW + x1);
                v10 = __ldg(xc + y1 * PW + x0);
                v11 = __ldg(xc + y1 * PW + x1);
            }

            float top = v00 + wx * (v01 - v00);
            float bot = v10 + wx * (v11 - v10);
            float v   = top + wy * (bot - top);

            int ly = py + i * 8;
            oc[(ty0 + ly) * PW + (tx0 + px)] = v;
        }
    }
}

extern "C" void kernel_launch(void* const* d_in, const int* in_sizes, int n_in,
                              void* d_out, int out_size)
{
    const float* x   = (const float*)d_in[0];
    const float* phi = (const float*)d_in[1];
    float* out = (float*)d_out;

    const int smem_bytes = 2 * TILE_FLOATS * sizeof(float);   // 53760 B
    static int configured = -1;
    if (configured < 0) {
        cudaFuncSetAttribute(pull_tile3_kernel,
                             cudaFuncAttributeMaxDynamicSharedMemorySize,
                             smem_bytes);
        configured = 1;
    }

    dim3 grid(PW / TW, PH / TH, PB);   // 8 x 8 x 8 = 512 blocks
    pull_tile3_kernel<<<grid, NT, smem_bytes>>>(x, phi, out);
}